// round 2
// baseline (speedup 1.0000x reference)
#include <cuda_runtime.h>

#define TT  4096     // T
#define DD  1024     // D
#define HH  16
#define DH  64
#define BHN 32       // B*H
#define ROWS 8192    // B*T
#define FD  512      // 2m
#define NSPLIT 16

// ---------------- scratch (device globals; no runtime allocation) ----------------
__device__ float g_Q[ROWS * DD];
__device__ float g_K[ROWS * DD];
__device__ float g_V[ROWS * DD];
__device__ float g_attn[ROWS * DD];
__device__ float g_Qf[BHN * TT * FD];
__device__ float g_Kf[BHN * TT * FD];
__device__ float g_KVpart[BHN * NSPLIT * FD * 65];
__device__ float g_KV[BHN * FD * 65];

// ---------------- fp32 GEMM:  C[M,N] = A[M,K] * B[N,K]^T  (both K-contiguous) ----
__global__ __launch_bounds__(256, 2) void gemm_nt(const float* __restrict__ A,
                                                  const float* __restrict__ B,
                                                  float* __restrict__ C,
                                                  int M, int N, int K) {
    __shared__ float As[16][128];
    __shared__ float Bs[16][128];
    const int tid = threadIdx.x;
    const int brow = blockIdx.y * 128;
    const int bcol = blockIdx.x * 128;
    const int ty = tid >> 4, tx = tid & 15;

    float acc[8][8];
#pragma unroll
    for (int i = 0; i < 8; i++)
#pragma unroll
        for (int j = 0; j < 8; j++) acc[i][j] = 0.f;

    const float* Ab = A + (size_t)brow * K;
    const float* Bb = B + (size_t)bcol * K;

    for (int k0 = 0; k0 < K; k0 += 16) {
        __syncthreads();
#pragma unroll
        for (int u = 0; u < 2; u++) {
            int idx = tid + u * 256;          // 0..511 float4 slots
            int row = idx >> 2;               // 0..127
            int c4  = (idx & 3) << 2;         // 0,4,8,12
            float4 va = *(const float4*)(Ab + (size_t)row * K + k0 + c4);
            As[c4 + 0][row] = va.x; As[c4 + 1][row] = va.y;
            As[c4 + 2][row] = va.z; As[c4 + 3][row] = va.w;
            float4 vb = *(const float4*)(Bb + (size_t)row * K + k0 + c4);
            Bs[c4 + 0][row] = vb.x; Bs[c4 + 1][row] = vb.y;
            Bs[c4 + 2][row] = vb.z; Bs[c4 + 3][row] = vb.w;
        }
        __syncthreads();
#pragma unroll
        for (int kk = 0; kk < 16; kk++) {
            float4 a0 = *(const float4*)&As[kk][ty * 4];
            float4 a1 = *(const float4*)&As[kk][64 + ty * 4];
            float4 b0 = *(const float4*)&Bs[kk][tx * 4];
            float4 b1 = *(const float4*)&Bs[kk][64 + tx * 4];
            float av[8] = {a0.x, a0.y, a0.z, a0.w, a1.x, a1.y, a1.z, a1.w};
            float bv[8] = {b0.x, b0.y, b0.z, b0.w, b1.x, b1.y, b1.z, b1.w};
#pragma unroll
            for (int i = 0; i < 8; i++)
#pragma unroll
                for (int j = 0; j < 8; j++)
                    acc[i][j] = fmaf(av[i], bv[j], acc[i][j]);
        }
    }
#pragma unroll
    for (int i = 0; i < 8; i++) {
        int r = brow + ((i < 4) ? (ty * 4 + i) : (64 + ty * 4 + (i - 4)));
        float4 o0 = make_float4(acc[i][0], acc[i][1], acc[i][2], acc[i][3]);
        float4 o1 = make_float4(acc[i][4], acc[i][5], acc[i][6], acc[i][7]);
        *(float4*)(C + (size_t)r * N + bcol + tx * 4) = o0;
        *(float4*)(C + (size_t)r * N + bcol + 64 + tx * 4) = o1;
    }
}

// ---------------- phi: QK[rows, D] -> feat[bh][t][512] ---------------------------
// feat[.., m]       = cos(q . rf_m) * exp(-|q|^2/2)/16
// feat[.., 256 + m] = sin(q . rf_m) * exp(-|q|^2/2)/16
__global__ __launch_bounds__(256) void phi_kernel(const float* __restrict__ QK,
                                                  const float* __restrict__ rf,
                                                  float* __restrict__ outF) {
    __shared__ float rfT[64][128];   // d-major half of rf (128 m rows)
    __shared__ float qsT[64][32];    // d-major q tile (32 t)
    __shared__ float scale_s[32];
    const int tid = threadIdx.x;
    const int bh = blockIdx.y;
    const int b = bh >> 4, h = bh & 15;
    const int t0 = blockIdx.x * 32;

    for (int i = tid; i < 32 * 64; i += 256) {
        int t = i >> 6, d = i & 63;
        qsT[d][t] = QK[(size_t)(b * TT + t0 + t) * DD + h * DH + d];
    }
    __syncthreads();
    if (tid < 32) {
        float ns = 0.f;
#pragma unroll
        for (int d = 0; d < 64; d++) { float q = qsT[d][tid]; ns = fmaf(q, q, ns); }
        scale_s[tid] = expf(-0.5f * ns) * 0.0625f;   // 1/sqrt(256) = 1/16
    }
    const int ty = tid >> 4, tx = tid & 15;   // t = ty*2 + {0,1}
    for (int half = 0; half < 2; half++) {
        __syncthreads();
        for (int i = tid; i < 128 * 64; i += 256) {
            int mrow = i >> 6, d = i & 63;
            rfT[d][mrow] = rf[(half * 128 + mrow) * 64 + d];
        }
        __syncthreads();
        float acc[2][8];
#pragma unroll
        for (int it = 0; it < 2; it++)
#pragma unroll
            for (int j = 0; j < 8; j++) acc[it][j] = 0.f;
#pragma unroll
        for (int d = 0; d < 64; d++) {
            float q0 = qsT[d][ty * 2 + 0];
            float q1 = qsT[d][ty * 2 + 1];
            float4 r0 = *(const float4*)&rfT[d][tx * 4];
            float4 r1 = *(const float4*)&rfT[d][64 + tx * 4];
            float rv[8] = {r0.x, r0.y, r0.z, r0.w, r1.x, r1.y, r1.z, r1.w};
#pragma unroll
            for (int j = 0; j < 8; j++) {
                acc[0][j] = fmaf(q0, rv[j], acc[0][j]);
                acc[1][j] = fmaf(q1, rv[j], acc[1][j]);
            }
        }
#pragma unroll
        for (int it = 0; it < 2; it++) {
            int t = ty * 2 + it;
            float sc = scale_s[t];
            size_t base = ((size_t)bh * TT + t0 + t) * FD;
#pragma unroll
            for (int j = 0; j < 8; j++) {
                int m = half * 128 + ((j < 4) ? (tx * 4 + j) : (64 + tx * 4 + (j - 4)));
                float s, c;
                sincosf(acc[it][j], &s, &c);
                outF[base + m]       = c * sc;
                outF[base + 256 + m] = s * sc;
            }
        }
    }
}

// ---------------- KV partial:  part[bh][split][f][0..63] = sum_t Kf[t,f] V[t,d]
//                               part[..][64]              = sum_t Kf[t,f]  (K_sum)
__global__ __launch_bounds__(512, 1) void kv_kernel(const float* __restrict__ Kf,
                                                    const float* __restrict__ V,
                                                    float* __restrict__ part) {
    __shared__ float Vs[32][64];
    const int tid = threadIdx.x;                 // tid == f
    const int bh = blockIdx.y, b = bh >> 4, h = bh & 15;
    const int split = blockIdx.x;
    const int tbase = split * (TT / NSPLIT);     // 256 t per block
    float acc[65];
#pragma unroll
    for (int d = 0; d < 65; d++) acc[d] = 0.f;

    for (int tc0 = 0; tc0 < TT / NSPLIT; tc0 += 32) {
        __syncthreads();
        for (int i = tid; i < 32 * 64; i += 512) {
            int t = i >> 6, d = i & 63;
            Vs[t][d] = V[(size_t)(b * TT + tbase + tc0 + t) * DD + h * DH + d];
        }
        __syncthreads();
        const float* kfp = Kf + ((size_t)bh * TT + tbase + tc0) * FD + tid;
        float kf_next = kfp[0];
#pragma unroll 4
        for (int t = 0; t < 32; t++) {
            float kf = kf_next;
            if (t < 31) kf_next = kfp[(size_t)(t + 1) * FD];
#pragma unroll
            for (int d = 0; d < 64; d += 4) {
                float4 v = *(const float4*)&Vs[t][d];
                acc[d + 0] = fmaf(kf, v.x, acc[d + 0]);
                acc[d + 1] = fmaf(kf, v.y, acc[d + 1]);
                acc[d + 2] = fmaf(kf, v.z, acc[d + 2]);
                acc[d + 3] = fmaf(kf, v.w, acc[d + 3]);
            }
            acc[64] += kf;
        }
    }
    float* p = part + (((size_t)bh * NSPLIT + split) * FD + tid) * 65;
#pragma unroll
    for (int d = 0; d < 65; d++) p[d] = acc[d];
}

// ---------------- deterministic reduce over splits -------------------------------
__global__ void kv_reduce(const float* __restrict__ part, float* __restrict__ KV) {
    const int bh = blockIdx.x;
    for (int i = threadIdx.x; i < FD * 65; i += blockDim.x) {
        float s = 0.f;
#pragma unroll
        for (int p = 0; p < NSPLIT; p++)
            s += part[((size_t)bh * NSPLIT + p) * FD * 65 + i];
        KV[(size_t)bh * FD * 65 + i] = s;
    }
}

// ---------------- QKV + Z + normalize:  attn[b*T+t, h*64+d] ----------------------
__global__ __launch_bounds__(256) void qkv_kernel(const float* __restrict__ Qf,
                                                  const float* __restrict__ KV,
                                                  float* __restrict__ attn) {
    __shared__ float Qfs[16][64];
    __shared__ float KVs[16][64];
    __shared__ float ksums[16];
    __shared__ float zs[64];
    const int tid = threadIdx.x;
    const int bh = blockIdx.y, b = bh >> 4, h = bh & 15;
    const int t0 = blockIdx.x * 64;
    const int ty = tid >> 4, tx = tid & 15;
    float acc[4][4];
#pragma unroll
    for (int i = 0; i < 4; i++)
#pragma unroll
        for (int j = 0; j < 4; j++) acc[i][j] = 0.f;
    float zacc = 0.f;

    for (int f0 = 0; f0 < FD; f0 += 16) {
        __syncthreads();
        for (int i = tid; i < 1024; i += 256) {
            int t = i >> 4, kk = i & 15;
            Qfs[kk][t] = Qf[((size_t)bh * TT + t0 + t) * FD + f0 + kk];
        }
        for (int i = tid; i < 1024; i += 256) {
            int kk = i >> 6, d = i & 63;
            KVs[kk][d] = KV[((size_t)bh * FD + f0 + kk) * 65 + d];
        }
        if (tid < 16) ksums[tid] = KV[((size_t)bh * FD + f0 + tid) * 65 + 64];
        __syncthreads();
#pragma unroll
        for (int kk = 0; kk < 16; kk++) {
            float4 a  = *(const float4*)&Qfs[kk][ty * 4];
            float4 bb = *(const float4*)&KVs[kk][tx * 4];
            float av[4] = {a.x, a.y, a.z, a.w};
            float bv[4] = {bb.x, bb.y, bb.z, bb.w};
#pragma unroll
            for (int i = 0; i < 4; i++)
#pragma unroll
                for (int j = 0; j < 4; j++)
                    acc[i][j] = fmaf(av[i], bv[j], acc[i][j]);
        }
        if (tid < 64) {
#pragma unroll
            for (int kk = 0; kk < 16; kk++)
                zacc = fmaf(Qfs[kk][tid], ksums[kk], zacc);
        }
    }
    __syncthreads();
    if (tid < 64) zs[tid] = fmaxf(zacc, 1e-6f);
    __syncthreads();
#pragma unroll
    for (int i = 0; i < 4; i++) {
        int t = ty * 4 + i;
        float invz = 1.f / zs[t];
        float4 o = make_float4(acc[i][0] * invz, acc[i][1] * invz,
                               acc[i][2] * invz, acc[i][3] * invz);
        *(float4*)(attn + (size_t)(b * TT + t0 + t) * DD + h * DH + tx * 4) = o;
    }
}

// ---------------- launch ----------------------------------------------------------
extern "C" void kernel_launch(void* const* d_in, const int* in_sizes, int n_in,
                              void* d_out, int out_size) {
    (void)in_sizes; (void)n_in; (void)out_size;
    const float* x  = (const float*)d_in[0];
    const float* wq = (const float*)d_in[1];
    const float* wk = (const float*)d_in[2];
    const float* wv = (const float*)d_in[3];
    const float* wo = (const float*)d_in[4];
    const float* rf = (const float*)d_in[5];
    float* out = (float*)d_out;

    float *Q, *K, *V, *Qf, *Kf, *attn, *part, *KV;
    cudaGetSymbolAddress((void**)&Q,    g_Q);
    cudaGetSymbolAddress((void**)&K,    g_K);
    cudaGetSymbolAddress((void**)&V,    g_V);
    cudaGetSymbolAddress((void**)&Qf,   g_Qf);
    cudaGetSymbolAddress((void**)&Kf,   g_Kf);
    cudaGetSymbolAddress((void**)&attn, g_attn);
    cudaGetSymbolAddress((void**)&part, g_KVpart);
    cudaGetSymbolAddress((void**)&KV,   g_KV);

    dim3 gg(DD / 128, ROWS / 128);          // (8, 64)
    gemm_nt<<<gg, 256>>>(x, wq, Q, ROWS, DD, DD);
    gemm_nt<<<gg, 256>>>(x, wk, K, ROWS, DD, DD);
    gemm_nt<<<gg, 256>>>(x, wv, V, ROWS, DD, DD);

    dim3 gp(TT / 32, BHN);                  // (128, 32)
    phi_kernel<<<gp, 256>>>(Q, rf, Qf);
    phi_kernel<<<gp, 256>>>(K, rf, Kf);

    kv_kernel<<<dim3(NSPLIT, BHN), 512>>>(Kf, V, part);
    kv_reduce<<<BHN, 256>>>(part, KV);

    qkv_kernel<<<dim3(TT / 64, BHN), 256>>>(Qf, KV, attn);

    gemm_nt<<<gg, 256>>>(attn, wo, out, ROWS, DD, DD);
}

// round 6
// speedup vs baseline: 1.4059x; 1.4059x over previous
#include <cuda_runtime.h>
#include <cuda_bf16.h>
#include <cstdint>

#define TT  4096     // T
#define DD  1024     // D
#define HH  16
#define DH  64
#define BHN 32       // B*H
#define ROWS 8192    // B*T
#define FD  512      // 2m
#define NSPLIT 16

// ---------------- scratch (device globals; no runtime allocation) ----------------
__device__ float g_Q[ROWS * DD];
__device__ float g_K[ROWS * DD];
__device__ float g_V[ROWS * DD];
__device__ float g_attn[ROWS * DD];
__device__ float g_Qf[BHN * TT * FD];
__device__ float g_Kf[BHN * TT * FD];
__device__ float g_KVpart[BHN * NSPLIT * FD * 65];
__device__ float g_KV[BHN * FD * 65];
__device__ __nv_bfloat16 g_Ahi[ROWS * DD];
__device__ __nv_bfloat16 g_Alo[ROWS * DD];
__device__ __nv_bfloat16 g_Whi[DD * DD];
__device__ __nv_bfloat16 g_Wlo[DD * DD];

// =================== base-target PTX helpers (no tcgen05!) =======================
__device__ __forceinline__ uint32_t smem_u32(const void* p) {
    uint32_t a;
    asm("{ .reg .u64 t; cvta.to.shared.u64 t, %1; cvt.u32.u64 %0, t; }" : "=r"(a) : "l"(p));
    return a;
}
#define CP_ASYNC16(saddr, gptr) \
    asm volatile("cp.async.cg.shared.global [%0], [%1], 16;" :: "r"(saddr), "l"(gptr))
#define CP_ASYNC_COMMIT() asm volatile("cp.async.commit_group;" ::: "memory")
#define CP_ASYNC_WAIT1()  asm volatile("cp.async.wait_group 1;" ::: "memory")
#define CP_ASYNC_WAIT0()  asm volatile("cp.async.wait_group 0;" ::: "memory")
#define LDMATRIX_X4(r, addr) \
    asm volatile("ldmatrix.sync.aligned.m8n8.x4.shared.b16 {%0,%1,%2,%3}, [%4];" \
        : "=r"((r)[0]), "=r"((r)[1]), "=r"((r)[2]), "=r"((r)[3]) : "r"(addr))
#define LDMATRIX_X2(r, addr) \
    asm volatile("ldmatrix.sync.aligned.m8n8.x2.shared.b16 {%0,%1}, [%2];" \
        : "=r"((r)[0]), "=r"((r)[1]) : "r"(addr))
#define MMA16816(c, a, b) \
    asm volatile("mma.sync.aligned.m16n8k16.row.col.f32.bf16.bf16.f32 " \
        "{%0,%1,%2,%3}, {%4,%5,%6,%7}, {%8,%9}, {%0,%1,%2,%3};" \
        : "+f"((c)[0]), "+f"((c)[1]), "+f"((c)[2]), "+f"((c)[3]) \
        : "r"((a)[0]), "r"((a)[1]), "r"((a)[2]), "r"((a)[3]), "r"((b)[0]), "r"((b)[1]))

// =================== HMMA bf16x3 split GEMM ======================================
// C[M,N] = A[M,K] * B[N,K]^T with A = Ahi+Alo, B = Bhi+Blo (bf16 splits of fp32).
// C += Ahi*Bhi + Ahi*Blo + Alo*Bhi  (fp32 accumulate in registers).
// CTA tile 128x128, 8 warps (2M x 4N => 64x32 per warp), K-chunk 32, 2-stage cp.async.
// Smem per stage: Ahi | Alo | Bhi | Blo, each 128 rows x 32 bf16 (64B rows),
// 16B chunks swizzled: c' = c ^ ((row>>1)&3)  -> conflict-free ldmatrix & stores.
#define G_STAGE 32768
#define G_AHI 0
#define G_ALO 8192
#define G_BHI 16384
#define G_BLO 24576
#define G_TOTAL (2 * G_STAGE)

__global__ __launch_bounds__(256)
void gemm_tc(const __nv_bfloat16* __restrict__ Ahi, const __nv_bfloat16* __restrict__ Alo,
             const __nv_bfloat16* __restrict__ Bhi, const __nv_bfloat16* __restrict__ Blo,
             float* __restrict__ C, int M, int N, int K) {
    extern __shared__ char smem[];
    const uint32_t sbase = smem_u32(smem);
    const int tid = threadIdx.x;
    const int wid = tid >> 5, lane = tid & 31;
    const int warpM = (wid >> 2) * 64;      // 0 or 64
    const int warpN = (wid & 3) * 32;       // 0,32,64,96
    const int brow = blockIdx.y * 128;
    const int bcol = blockIdx.x * 128;

    float acc[4][4][4];
#pragma unroll
    for (int i = 0; i < 4; i++)
#pragma unroll
        for (int j = 0; j < 4; j++)
#pragma unroll
            for (int r = 0; r < 4; r++) acc[i][j][r] = 0.f;

    // per-thread load coordinates (2 chunks of 16B per tile per thread)
    const int r0 = tid >> 2, c0 = tid & 3;               // chunk idx tid
    const int r1 = (tid + 256) >> 2, c1 = c0;            // chunk idx tid+256
    const uint32_t so0 = (uint32_t)(r0 * 64 + ((c0 ^ ((r0 >> 1) & 3)) * 16));
    const uint32_t so1 = (uint32_t)(r1 * 64 + ((c1 ^ ((r1 >> 1) & 3)) * 16));

    const int nchunk = K >> 5;

#define ISSUE_CHUNK(ch, stg) do { \
    const int _k0 = (ch) << 5; \
    const uint32_t _st = sbase + (stg) * G_STAGE; \
    const size_t _ga0 = (size_t)(brow + r0) * K + _k0 + c0 * 8; \
    const size_t _ga1 = (size_t)(brow + r1) * K + _k0 + c1 * 8; \
    const size_t _gb0 = (size_t)(bcol + r0) * K + _k0 + c0 * 8; \
    const size_t _gb1 = (size_t)(bcol + r1) * K + _k0 + c1 * 8; \
    CP_ASYNC16(_st + G_AHI + so0, Ahi + _ga0); \
    CP_ASYNC16(_st + G_AHI + so1, Ahi + _ga1); \
    CP_ASYNC16(_st + G_ALO + so0, Alo + _ga0); \
    CP_ASYNC16(_st + G_ALO + so1, Alo + _ga1); \
    CP_ASYNC16(_st + G_BHI + so0, Bhi + _gb0); \
    CP_ASYNC16(_st + G_BHI + so1, Bhi + _gb1); \
    CP_ASYNC16(_st + G_BLO + so0, Blo + _gb0); \
    CP_ASYNC16(_st + G_BLO + so1, Blo + _gb1); \
    CP_ASYNC_COMMIT(); \
} while (0)

    ISSUE_CHUNK(0, 0);

    for (int ch = 0; ch < nchunk; ch++) {
        const int s = ch & 1;
        if (ch + 1 < nchunk) { ISSUE_CHUNK(ch + 1, s ^ 1); CP_ASYNC_WAIT1(); }
        else                 { CP_ASYNC_WAIT0(); }
        __syncthreads();

        const uint32_t st = sbase + s * G_STAGE;
#pragma unroll
        for (int kk = 0; kk < 2; kk++) {           // k sub-chunks of 16
            const int cb = kk * 2;
            // ---- B fragments (hi & lo) ----
            uint32_t bh[4][2], bl[4][2];
#pragma unroll
            for (int ni = 0; ni < 4; ni++) {
                const int n = warpN + ni * 8 + (lane & 7);
                const int chk = cb + ((lane >> 3) & 1);
                const uint32_t ad = st + G_BHI + (uint32_t)(n * 64 + ((chk ^ ((n >> 1) & 3)) * 16));
                LDMATRIX_X2(bh[ni], ad);
                LDMATRIX_X2(bl[ni], ad + 8192);
            }
            // ---- A-hi fragments, 2 passes ----
            uint32_t af[4][4];
#pragma unroll
            for (int mi = 0; mi < 4; mi++) {
                const int m = warpM + mi * 16 + (lane & 15);
                const int chk = cb + (lane >> 4);
                const uint32_t ad = st + G_AHI + (uint32_t)(m * 64 + ((chk ^ ((m >> 1) & 3)) * 16));
                LDMATRIX_X4(af[mi], ad);
            }
#pragma unroll
            for (int mi = 0; mi < 4; mi++)
#pragma unroll
                for (int ni = 0; ni < 4; ni++) MMA16816(acc[mi][ni], af[mi], bh[ni]);
#pragma unroll
            for (int mi = 0; mi < 4; mi++)
#pragma unroll
                for (int ni = 0; ni < 4; ni++) MMA16816(acc[mi][ni], af[mi], bl[ni]);
            // ---- A-lo fragments, 1 pass ----
#pragma unroll
            for (int mi = 0; mi < 4; mi++) {
                const int m = warpM + mi * 16 + (lane & 15);
                const int chk = cb + (lane >> 4);
                const uint32_t ad = st + G_ALO + (uint32_t)(m * 64 + ((chk ^ ((m >> 1) & 3)) * 16));
                LDMATRIX_X4(af[mi], ad);
            }
#pragma unroll
            for (int mi = 0; mi < 4; mi++)
#pragma unroll
                for (int ni = 0; ni < 4; ni++) MMA16816(acc[mi][ni], af[mi], bh[ni]);
        }
        __syncthreads();
    }
#undef ISSUE_CHUNK

    // ---- epilogue ----
#pragma unroll
    for (int mi = 0; mi < 4; mi++) {
        const int row = brow + warpM + mi * 16 + (lane >> 2);
#pragma unroll
        for (int ni = 0; ni < 4; ni++) {
            const int col = bcol + warpN + ni * 8 + (lane & 3) * 2;
            *(float2*)(C + (size_t)row * N + col)       = make_float2(acc[mi][ni][0], acc[mi][ni][1]);
            *(float2*)(C + (size_t)(row + 8) * N + col) = make_float2(acc[mi][ni][2], acc[mi][ni][3]);
        }
    }
}

// ---------------- fp32 -> bf16 hi/lo split (vectorized) --------------------------
__global__ __launch_bounds__(256) void split_kernel(const float* __restrict__ src,
                                                    __nv_bfloat16* __restrict__ hi,
                                                    __nv_bfloat16* __restrict__ lo,
                                                    int n4) {
    int i = blockIdx.x * blockDim.x + threadIdx.x;
    if (i >= n4) return;
    float4 v = ((const float4*)src)[i];
    __nv_bfloat16 hx = __float2bfloat16(v.x);
    __nv_bfloat16 hy = __float2bfloat16(v.y);
    __nv_bfloat16 hz = __float2bfloat16(v.z);
    __nv_bfloat16 hw = __float2bfloat16(v.w);
    __nv_bfloat162* hp = (__nv_bfloat162*)hi;
    __nv_bfloat162* lp = (__nv_bfloat162*)lo;
    hp[2 * i + 0] = __nv_bfloat162{hx, hy};
    hp[2 * i + 1] = __nv_bfloat162{hz, hw};
    lp[2 * i + 0] = __nv_bfloat162{__float2bfloat16(v.x - __bfloat162float(hx)),
                                   __float2bfloat16(v.y - __bfloat162float(hy))};
    lp[2 * i + 1] = __nv_bfloat162{__float2bfloat16(v.z - __bfloat162float(hz)),
                                   __float2bfloat16(v.w - __bfloat162float(hw))};
}

// ---------------- phi: QK[rows, D] -> feat[bh][t][512] ---------------------------
__global__ __launch_bounds__(256) void phi_kernel(const float* __restrict__ QK,
                                                  const float* __restrict__ rf,
                                                  float* __restrict__ outF) {
    __shared__ float rfT[64][128];   // d-major half of rf (128 m rows)
    __shared__ float qsT[64][32];    // d-major q tile (32 t)
    __shared__ float scale_s[32];
    const int tid = threadIdx.x;
    const int bh = blockIdx.y;
    const int b = bh >> 4, h = bh & 15;
    const int t0 = blockIdx.x * 32;

    for (int i = tid; i < 32 * 64; i += 256) {
        int t = i >> 6, d = i & 63;
        qsT[d][t] = QK[(size_t)(b * TT + t0 + t) * DD + h * DH + d];
    }
    __syncthreads();
    if (tid < 32) {
        float ns = 0.f;
#pragma unroll
        for (int d = 0; d < 64; d++) { float q = qsT[d][tid]; ns = fmaf(q, q, ns); }
        scale_s[tid] = expf(-0.5f * ns) * 0.0625f;   // 1/sqrt(256) = 1/16
    }
    const int ty = tid >> 4, tx = tid & 15;   // t = ty*2 + {0,1}
    for (int half = 0; half < 2; half++) {
        __syncthreads();
        for (int i = tid; i < 128 * 64; i += 256) {
            int mrow = i >> 6, d = i & 63;
            rfT[d][mrow] = rf[(half * 128 + mrow) * 64 + d];
        }
        __syncthreads();
        float acc[2][8];
#pragma unroll
        for (int it = 0; it < 2; it++)
#pragma unroll
            for (int j = 0; j < 8; j++) acc[it][j] = 0.f;
#pragma unroll
        for (int d = 0; d < 64; d++) {
            float q0 = qsT[d][ty * 2 + 0];
            float q1 = qsT[d][ty * 2 + 1];
            float4 rr0 = *(const float4*)&rfT[d][tx * 4];
            float4 rr1 = *(const float4*)&rfT[d][64 + tx * 4];
            float rv[8] = {rr0.x, rr0.y, rr0.z, rr0.w, rr1.x, rr1.y, rr1.z, rr1.w};
#pragma unroll
            for (int j = 0; j < 8; j++) {
                acc[0][j] = fmaf(q0, rv[j], acc[0][j]);
                acc[1][j] = fmaf(q1, rv[j], acc[1][j]);
            }
        }
#pragma unroll
        for (int it = 0; it < 2; it++) {
            int t = ty * 2 + it;
            float sc = scale_s[t];
            size_t base = ((size_t)bh * TT + t0 + t) * FD;
#pragma unroll
            for (int j = 0; j < 8; j++) {
                int m = half * 128 + ((j < 4) ? (tx * 4 + j) : (64 + tx * 4 + (j - 4)));
                float s, c;
                sincosf(acc[it][j], &s, &c);
                outF[base + m]       = c * sc;
                outF[base + 256 + m] = s * sc;
            }
        }
    }
}

// ---------------- KV partial ------------------------------------------------------
__global__ __launch_bounds__(512, 1) void kv_kernel(const float* __restrict__ Kf,
                                                    const float* __restrict__ V,
                                                    float* __restrict__ part) {
    __shared__ float Vs[32][64];
    const int tid = threadIdx.x;                 // tid == f
    const int bh = blockIdx.y, b = bh >> 4, h = bh & 15;
    const int split = blockIdx.x;
    const int tbase = split * (TT / NSPLIT);     // 256 t per block
    float acc[65];
#pragma unroll
    for (int d = 0; d < 65; d++) acc[d] = 0.f;

    for (int tc0 = 0; tc0 < TT / NSPLIT; tc0 += 32) {
        __syncthreads();
        for (int i = tid; i < 32 * 64; i += 512) {
            int t = i >> 6, d = i & 63;
            Vs[t][d] = V[(size_t)(b * TT + tbase + tc0 + t) * DD + h * DH + d];
        }
        __syncthreads();
        const float* kfp = Kf + ((size_t)bh * TT + tbase + tc0) * FD + tid;
        float kf_next = kfp[0];
#pragma unroll 4
        for (int t = 0; t < 32; t++) {
            float kf = kf_next;
            if (t < 31) kf_next = kfp[(size_t)(t + 1) * FD];
#pragma unroll
            for (int d = 0; d < 64; d += 4) {
                float4 v = *(const float4*)&Vs[t][d];
                acc[d + 0] = fmaf(kf, v.x, acc[d + 0]);
                acc[d + 1] = fmaf(kf, v.y, acc[d + 1]);
                acc[d + 2] = fmaf(kf, v.z, acc[d + 2]);
                acc[d + 3] = fmaf(kf, v.w, acc[d + 3]);
            }
            acc[64] += kf;
        }
    }
    float* p = part + (((size_t)bh * NSPLIT + split) * FD + tid) * 65;
#pragma unroll
    for (int d = 0; d < 65; d++) p[d] = acc[d];
}

// ---------------- deterministic reduce over splits -------------------------------
__global__ void kv_reduce(const float* __restrict__ part, float* __restrict__ KV) {
    const int bh = blockIdx.x;
    for (int i = threadIdx.x; i < FD * 65; i += blockDim.x) {
        float s = 0.f;
#pragma unroll
        for (int p = 0; p < NSPLIT; p++)
            s += part[((size_t)bh * NSPLIT + p) * FD * 65 + i];
        KV[(size_t)bh * FD * 65 + i] = s;
    }
}

// ---------------- QKV + Z + normalize --------------------------------------------
__global__ __launch_bounds__(256) void qkv_kernel(const float* __restrict__ Qf,
                                                  const float* __restrict__ KV,
                                                  float* __restrict__ attn) {
    __shared__ float Qfs[16][64];
    __shared__ float KVs[16][64];
    __shared__ float ksums[16];
    __shared__ float zs[64];
    const int tid = threadIdx.x;
    const int bh = blockIdx.y, b = bh >> 4, h = bh & 15;
    const int t0 = blockIdx.x * 64;
    const int ty = tid >> 4, tx = tid & 15;
    float acc[4][4];
#pragma unroll
    for (int i = 0; i < 4; i++)
#pragma unroll
        for (int j = 0; j < 4; j++) acc[i][j] = 0.f;
    float zacc = 0.f;

    for (int f0 = 0; f0 < FD; f0 += 16) {
        __syncthreads();
        for (int i = tid; i < 1024; i += 256) {
            int t = i >> 4, kk = i & 15;
            Qfs[kk][t] = Qf[((size_t)bh * TT + t0 + t) * FD + f0 + kk];
        }
        for (int i = tid; i < 1024; i += 256) {
            int kk = i >> 6, d = i & 63;
            KVs[kk][d] = KV[((size_t)bh * FD + f0 + kk) * 65 + d];
        }
        if (tid < 16) ksums[tid] = KV[((size_t)bh * FD + f0 + tid) * 65 + 64];
        __syncthreads();
#pragma unroll
        for (int kk = 0; kk < 16; kk++) {
            float4 a  = *(const float4*)&Qfs[kk][ty * 4];
            float4 bb = *(const float4*)&KVs[kk][tx * 4];
            float av[4] = {a.x, a.y, a.z, a.w};
            float bv[4] = {bb.x, bb.y, bb.z, bb.w};
#pragma unroll
            for (int i = 0; i < 4; i++)
#pragma unroll
                for (int j = 0; j < 4; j++)
                    acc[i][j] = fmaf(av[i], bv[j], acc[i][j]);
        }
        if (tid < 64) {
#pragma unroll
            for (int kk = 0; kk < 16; kk++)
                zacc = fmaf(Qfs[kk][tid], ksums[kk], zacc);
        }
    }
    __syncthreads();
    if (tid < 64) zs[tid] = fmaxf(zacc, 1e-6f);
    __syncthreads();
#pragma unroll
    for (int i = 0; i < 4; i++) {
        int t = ty * 4 + i;
        float invz = 1.f / zs[t];
        float4 o = make_float4(acc[i][0] * invz, acc[i][1] * invz,
                               acc[i][2] * invz, acc[i][3] * invz);
        *(float4*)(attn + (size_t)(b * TT + t0 + t) * DD + h * DH + tx * 4) = o;
    }
}

// ---------------- launch ----------------------------------------------------------
extern "C" void kernel_launch(void* const* d_in, const int* in_sizes, int n_in,
                              void* d_out, int out_size) {
    (void)in_sizes; (void)n_in; (void)out_size;
    const float* x  = (const float*)d_in[0];
    const float* wq = (const float*)d_in[1];
    const float* wk = (const float*)d_in[2];
    const float* wv = (const float*)d_in[3];
    const float* wo = (const float*)d_in[4];
    const float* rf = (const float*)d_in[5];
    float* out = (float*)d_out;

    float *Q, *K, *V, *Qf, *Kf, *attn, *part, *KV;
    __nv_bfloat16 *Ahi, *Alo, *Whi, *Wlo;
    cudaGetSymbolAddress((void**)&Q,    g_Q);
    cudaGetSymbolAddress((void**)&K,    g_K);
    cudaGetSymbolAddress((void**)&V,    g_V);
    cudaGetSymbolAddress((void**)&Qf,   g_Qf);
    cudaGetSymbolAddress((void**)&Kf,   g_Kf);
    cudaGetSymbolAddress((void**)&attn, g_attn);
    cudaGetSymbolAddress((void**)&part, g_KVpart);
    cudaGetSymbolAddress((void**)&KV,   g_KV);
    cudaGetSymbolAddress((void**)&Ahi,  g_Ahi);
    cudaGetSymbolAddress((void**)&Alo,  g_Alo);
    cudaGetSymbolAddress((void**)&Whi,  g_Whi);
    cudaGetSymbolAddress((void**)&Wlo,  g_Wlo);

    cudaFuncSetAttribute(gemm_tc, cudaFuncAttributeMaxDynamicSharedMemorySize, G_TOTAL);

    const int nX4 = ROWS * DD / 4;   // 2097152
    const int nW4 = DD * DD / 4;     // 262144
    dim3 gg(DD / 128, ROWS / 128);   // (8, 64)

    // x split once, reused by the 3 projections
    split_kernel<<<nX4 / 256, 256>>>(x, Ahi, Alo, nX4);

    split_kernel<<<nW4 / 256, 256>>>(wq, Whi, Wlo, nW4);
    gemm_tc<<<gg, 256, G_TOTAL>>>(Ahi, Alo, Whi, Wlo, Q, ROWS, DD, DD);
    split_kernel<<<nW4 / 256, 256>>>(wk, Whi, Wlo, nW4);
    gemm_tc<<<gg, 256, G_TOTAL>>>(Ahi, Alo, Whi, Wlo, K, ROWS, DD, DD);
    split_kernel<<<nW4 / 256, 256>>>(wv, Whi, Wlo, nW4);
    gemm_tc<<<gg, 256, G_TOTAL>>>(Ahi, Alo, Whi, Wlo, V, ROWS, DD, DD);

    dim3 gp(TT / 32, BHN);                  // (128, 32)
    phi_kernel<<<gp, 256>>>(Q, rf, Qf);
    phi_kernel<<<gp, 256>>>(K, rf, Kf);

    kv_kernel<<<dim3(NSPLIT, BHN), 512>>>(Kf, V, part);
    kv_reduce<<<BHN, 256>>>(part, KV);

    qkv_kernel<<<dim3(TT / 64, BHN), 256>>>(Qf, KV, attn);

    // output projection: attn reuses the A-split buffers
    split_kernel<<<nX4 / 256, 256>>>(attn, Ahi, Alo, nX4);
    split_kernel<<<nW4 / 256, 256>>>(wo, Whi, Wlo, nW4);
    gemm_tc<<<gg, 256, G_TOTAL>>>(Ahi, Alo, Whi, Wlo, out, ROWS, DD, DD);
}